// round 12
// baseline (speedup 1.0000x reference)
#include <cuda_runtime.h>
#include <cstdint>

// ---------------------------------------------------------------------------
// CurveChannel — dual-path streaming experiment.
// Even CTAs read their 256-group tile via cp.async.bulk (TMA queue -> smem);
// odd CTAs read theirs via front-batched LDG.128 (LSU/L1tex path). Both kinds
// co-reside on each SM, so both load paths' outstanding-transaction pools are
// exercised concurrently. If the ~3 TB/s cold-read wall is per-path capacity,
// this roughly doubles it; if the wall is shared (LTS/MSHR/DRAM), it's flat.
// Params compacted per-warp with ballot+shfl; no block barrier on LDG CTAs.
// ---------------------------------------------------------------------------

#define NPTS   16
#define IN_CH  3
#define HW4    (512 * 512 / 4)        // float4 groups per (b,c) plane
#define TPB    128
#define GPC    256                    // output float4 groups per CTA
#define CH_BYTES (GPC * 16)           // 4096 per channel per CTA
#define BLOCKS_PER_BATCH (HW4 / GPC)  // 256
#define SMEM_MBAR 0
#define SMEM_DATA 128
#define SMEM_TOTAL (SMEM_DATA + IN_CH * CH_BYTES)   // 12416

__device__ __forceinline__ uint32_t smem_u32(const void* p) {
    uint32_t a;
    asm("{ .reg .u64 t; cvta.to.shared.u64 t, %1; cvt.u32.u64 %0, t; }"
        : "=r"(a) : "l"(p));
    return a;
}
__device__ __forceinline__ void mbar_init(uint32_t mbar, uint32_t count) {
    asm volatile("mbarrier.init.shared.b64 [%0], %1;" :: "r"(mbar), "r"(count) : "memory");
}
__device__ __forceinline__ void fence_proxy_async_cta() {
    asm volatile("fence.proxy.async.shared::cta;" ::: "memory");
}
__device__ __forceinline__ void mbar_expect_tx(uint32_t mbar, uint32_t bytes) {
    asm volatile("mbarrier.arrive.expect_tx.shared.b64 _, [%0], %1;"
                 :: "r"(mbar), "r"(bytes) : "memory");
}
__device__ __forceinline__ void bulk_ld(uint32_t dst_smem, const void* src, uint32_t bytes,
                                        uint32_t mbar) {
    asm volatile("cp.async.bulk.shared::cluster.global.mbarrier::complete_tx::bytes "
                 "[%0], [%1], %2, [%3];"
                 :: "r"(dst_smem), "l"(src), "r"(bytes), "r"(mbar) : "memory");
}
__device__ __forceinline__ void mbar_wait(uint32_t mbar, uint32_t parity) {
    uint32_t done;
    asm volatile(
        "{\n\t.reg .pred p;\n\t"
        "mbarrier.try_wait.parity.acquire.cta.shared::cta.b64 p, [%1], %2;\n\t"
        "selp.b32 %0, 1, 0, p;\n\t}"
        : "=r"(done) : "r"(mbar), "r"(parity) : "memory");
    if (!done) {
        asm volatile(
            "{\n\t.reg .pred P1;\n\t"
            "W_%=:\n\t"
            "mbarrier.try_wait.parity.acquire.cta.shared::cta.b64 P1, [%0], %1, 0x989680;\n\t"
            "@P1 bra.uni D_%=;\n\t"
            "bra.uni W_%=;\n\t"
            "D_%=:\n\t}"
            :: "r"(mbar), "r"(parity) : "memory");
    }
}

__global__ __launch_bounds__(TPB) void curve_dual(
    const float* __restrict__ x,       // (8, 3, 512, 512)
    const float* __restrict__ shift,   // (NPTS, C)
    const float* __restrict__ slopes,  // (NPTS, C)
    const float* __restrict__ conv_w,  // (C,)
    const float* __restrict__ conv_b,  // (1,)
    float* __restrict__ out)           // (8, 1, 512, 512)
{
    extern __shared__ char smem[];
    const uint32_t sb  = smem_u32(smem);
    const int tid  = threadIdx.x;
    const int lane = tid & 31;
    const int wid  = tid >> 5;
    const bool use_tma = (blockIdx.x & 1) == 0;

    const int b   = blockIdx.x / BLOCKS_PER_BATCH;
    const int seg = blockIdx.x % BLOCKS_PER_BATCH;
    const float4* xp = reinterpret_cast<const float4*>(x) +
                       (size_t)b * (IN_CH * HW4) + (size_t)seg * GPC;

    float4 xv0, xv1, xv2, xv0b, xv1b, xv2b;

    if (use_tma) {
        // ---- TMA path: init + fire 3x4KB copies before any sync ----
        if (tid == 0) {
            mbar_init(sb + SMEM_MBAR, 1);
            fence_proxy_async_cta();
            mbar_expect_tx(sb + SMEM_MBAR, IN_CH * CH_BYTES);
        }
        __syncwarp();
        if (wid == 0 && lane < IN_CH)
            bulk_ld(sb + SMEM_DATA + lane * CH_BYTES,
                    (const void*)(xp + (size_t)lane * HW4),
                    CH_BYTES, sb + SMEM_MBAR);
    } else {
        // ---- LDG path: 6 independent front-batched LDG.128 ----
        xv0  = __ldg(&xp[0 * HW4 + tid]);
        xv1  = __ldg(&xp[1 * HW4 + tid]);
        xv2  = __ldg(&xp[2 * HW4 + tid]);
        xv0b = __ldg(&xp[0 * HW4 + TPB + tid]);
        xv1b = __ldg(&xp[1 * HW4 + TPB + tid]);
        xv2b = __ldg(&xp[2 * HW4 + TPB + tid]);
    }

    // ---- per-warp param compaction (loads in flight) ----
    const bool pl = (lane < NPTS);
    float sl0 = pl ? __ldg(&slopes[lane * IN_CH + 0]) : 0.0f;
    float sl1 = pl ? __ldg(&slopes[lane * IN_CH + 1]) : 0.0f;
    float sl2 = pl ? __ldg(&slopes[lane * IN_CH + 2]) : 0.0f;
    float sh0 = pl ? __ldg(&shift [lane * IN_CH + 0]) : 0.0f;
    float sh1 = pl ? __ldg(&shift [lane * IN_CH + 1]) : 0.0f;
    float sh2 = pl ? __ldg(&shift [lane * IN_CH + 2]) : 0.0f;
    const float w0   = __ldg(&conv_w[0]);
    const float w1   = __ldg(&conv_w[1]);
    const float w2   = __ldg(&conv_w[2]);
    const float bias = __ldg(&conv_b[0]);

    unsigned m0 = __ballot_sync(0xFFFFFFFFu, sl0 != 0.0f);
    unsigned m1 = __ballot_sync(0xFFFFFFFFu, sl1 != 0.0f);
    unsigned m2 = __ballot_sync(0xFFFFFFFFu, sl2 != 0.0f);

    if (use_tma) {
        __syncthreads();                 // mbar init visible to all warps
        mbar_wait(sb + SMEM_MBAR, 0);
        const float4* sp = reinterpret_cast<const float4*>(smem + SMEM_DATA);
        xv0  = sp[0 * GPC + tid];
        xv1  = sp[1 * GPC + tid];
        xv2  = sp[2 * GPC + tid];
        xv0b = sp[0 * GPC + TPB + tid];
        xv1b = sp[1 * GPC + TPB + tid];
        xv2b = sp[2 * GPC + TPB + tid];
    }

    float4 acc  = make_float4(bias, bias, bias, bias);
    float4 accb = make_float4(bias, bias, bias, bias);

    while (m0) {
        int src = __ffs(m0) - 1; m0 &= m0 - 1;
        float sh = __shfl_sync(0xFFFFFFFFu, sh0, src);
        float ws = __shfl_sync(0xFFFFFFFFu, sl0, src) * w0;
        acc.x  = fmaf(ws, fmaxf(xv0.x  - sh, 0.0f), acc.x);
        acc.y  = fmaf(ws, fmaxf(xv0.y  - sh, 0.0f), acc.y);
        acc.z  = fmaf(ws, fmaxf(xv0.z  - sh, 0.0f), acc.z);
        acc.w  = fmaf(ws, fmaxf(xv0.w  - sh, 0.0f), acc.w);
        accb.x = fmaf(ws, fmaxf(xv0b.x - sh, 0.0f), accb.x);
        accb.y = fmaf(ws, fmaxf(xv0b.y - sh, 0.0f), accb.y);
        accb.z = fmaf(ws, fmaxf(xv0b.z - sh, 0.0f), accb.z);
        accb.w = fmaf(ws, fmaxf(xv0b.w - sh, 0.0f), accb.w);
    }
    while (m1) {
        int src = __ffs(m1) - 1; m1 &= m1 - 1;
        float sh = __shfl_sync(0xFFFFFFFFu, sh1, src);
        float ws = __shfl_sync(0xFFFFFFFFu, sl1, src) * w1;
        acc.x  = fmaf(ws, fmaxf(xv1.x  - sh, 0.0f), acc.x);
        acc.y  = fmaf(ws, fmaxf(xv1.y  - sh, 0.0f), acc.y);
        acc.z  = fmaf(ws, fmaxf(xv1.z  - sh, 0.0f), acc.z);
        acc.w  = fmaf(ws, fmaxf(xv1.w  - sh, 0.0f), acc.w);
        accb.x = fmaf(ws, fmaxf(xv1b.x - sh, 0.0f), accb.x);
        accb.y = fmaf(ws, fmaxf(xv1b.y - sh, 0.0f), accb.y);
        accb.z = fmaf(ws, fmaxf(xv1b.z - sh, 0.0f), accb.z);
        accb.w = fmaf(ws, fmaxf(xv1b.w - sh, 0.0f), accb.w);
    }
    while (m2) {
        int src = __ffs(m2) - 1; m2 &= m2 - 1;
        float sh = __shfl_sync(0xFFFFFFFFu, sh2, src);
        float ws = __shfl_sync(0xFFFFFFFFu, sl2, src) * w2;
        acc.x  = fmaf(ws, fmaxf(xv2.x  - sh, 0.0f), acc.x);
        acc.y  = fmaf(ws, fmaxf(xv2.y  - sh, 0.0f), acc.y);
        acc.z  = fmaf(ws, fmaxf(xv2.z  - sh, 0.0f), acc.z);
        acc.w  = fmaf(ws, fmaxf(xv2.w  - sh, 0.0f), acc.w);
        accb.x = fmaf(ws, fmaxf(xv2b.x - sh, 0.0f), accb.x);
        accb.y = fmaf(ws, fmaxf(xv2b.y - sh, 0.0f), accb.y);
        accb.z = fmaf(ws, fmaxf(xv2b.z - sh, 0.0f), accb.z);
        accb.w = fmaf(ws, fmaxf(xv2b.w - sh, 0.0f), accb.w);
    }

    acc.x  = fminf(fmaxf(acc.x,  0.0f), 1.0f);
    acc.y  = fminf(fmaxf(acc.y,  0.0f), 1.0f);
    acc.z  = fminf(fmaxf(acc.z,  0.0f), 1.0f);
    acc.w  = fminf(fmaxf(acc.w,  0.0f), 1.0f);
    accb.x = fminf(fmaxf(accb.x, 0.0f), 1.0f);
    accb.y = fminf(fmaxf(accb.y, 0.0f), 1.0f);
    accb.z = fminf(fmaxf(accb.z, 0.0f), 1.0f);
    accb.w = fminf(fmaxf(accb.w, 0.0f), 1.0f);

    float4* op = reinterpret_cast<float4*>(out) +
                 (size_t)b * HW4 + (size_t)seg * GPC + tid;
    op[0]   = acc;
    op[TPB] = accb;
}

extern "C" void kernel_launch(void* const* d_in, const int* in_sizes, int n_in,
                              void* d_out, int out_size)
{
    const float* x      = (const float*)d_in[0];
    const float* shift  = (const float*)d_in[1];
    const float* slopes = (const float*)d_in[2];
    const float* conv_w = (const float*)d_in[3];
    const float* conv_b = (const float*)d_in[4];
    float* out = (float*)d_out;

    static bool attr_set = false;
    if (!attr_set) {
        cudaFuncSetAttribute(curve_dual,
                             cudaFuncAttributeMaxDynamicSharedMemorySize,
                             SMEM_TOTAL);
        attr_set = true;
    }

    const int total_groups = out_size / 4;       // 524288
    const int blocks = total_groups / GPC;       // 2048
    curve_dual<<<blocks, TPB, SMEM_TOTAL>>>(x, shift, slopes, conv_w, conv_b, out);
}